// round 2
// baseline (speedup 1.0000x reference)
#include <cuda_runtime.h>
#include <cstdint>

#define BSZ     4
#define SEQ     4096
#define DIM     4096
#define NHEADS  32
#define NKV     8
#define HD      128

#define TILE_M  128
#define TILE_N  128
#define TILE_K  32
#define SSTR    36          // padded smem stride (floats): bank = (4*row + k) % 32, conflict-free
#define THREADS 128

static __device__ __forceinline__ uint32_t f2tf(float f) {
    uint32_t u;
    asm("cvt.rna.tf32.f32 %0, %1;" : "=r"(u) : "f"(f));
    return u;
}

__global__ void __launch_bounds__(THREADS, 2)
qkv_rope_kernel(const float* __restrict__ x,  const float* __restrict__ wq,
                const float* __restrict__ wk, const float* __restrict__ wv,
                const float* __restrict__ cosT, const float* __restrict__ sinT,
                float* __restrict__ out)
{
    extern __shared__ float smem[];                 // [2][A:128*36 | B:128*36]
    const int BUF = TILE_M * SSTR + TILE_N * SSTR;  // 9216 floats per buffer

    const int t    = threadIdx.x;
    const int head = blockIdx.x;        // 0..47 : one 128-col tile == one head
    const int m0   = blockIdx.y * TILE_M;

    const float* w;
    int n0;
    if (head < NHEADS)            { w = wq; n0 = head * HD; }
    else if (head < NHEADS + NKV) { w = wk; n0 = (head - NHEADS) * HD; }
    else                          { w = wv; n0 = (head - NHEADS - NKV) * HD; }

    const uint32_t sb = (uint32_t)__cvta_generic_to_shared(smem);

    auto stage = [&](int kt, int buf) {
        const float* asrc = x + (size_t)m0 * DIM + kt * TILE_K;
        const float* bsrc = w + (size_t)n0 * DIM + kt * TILE_K;
        uint32_t abase = sb + (uint32_t)buf * BUF * 4u;
        uint32_t bbase = abase + TILE_M * SSTR * 4u;
        #pragma unroll
        for (int j = 0; j < 8; j++) {
            int f = t + j * THREADS;
            int row = f >> 3, c4 = f & 7;
            uint32_t d = abase + (uint32_t)(row * SSTR + c4 * 4) * 4u;
            const float* s = asrc + (size_t)row * DIM + c4 * 4;
            asm volatile("cp.async.cg.shared.global [%0], [%1], 16;\n" :: "r"(d), "l"(s));
        }
        #pragma unroll
        for (int j = 0; j < 8; j++) {
            int f = t + j * THREADS;
            int row = f >> 3, c4 = f & 7;
            uint32_t d = bbase + (uint32_t)(row * SSTR + c4 * 4) * 4u;
            const float* s = bsrc + (size_t)row * DIM + c4 * 4;
            asm volatile("cp.async.cg.shared.global [%0], [%1], 16;\n" :: "r"(d), "l"(s));
        }
        asm volatile("cp.async.commit_group;\n");
    };

    const int lane = t & 31, wid = t >> 5;
    const int wm = wid & 1, wn = wid >> 1;      // 2x2 warps, each 64x64
    const int g  = lane >> 2, t4 = lane & 3;

    float acc[4][8][4];
    #pragma unroll
    for (int a = 0; a < 4; a++)
        #pragma unroll
        for (int b = 0; b < 8; b++)
            #pragma unroll
            for (int c = 0; c < 4; c++) acc[a][b][c] = 0.f;

    const int NKT = DIM / TILE_K;   // 128
    stage(0, 0);

    for (int kt = 0; kt < NKT; kt++) {
        if (kt + 1 < NKT) {
            stage(kt + 1, (kt + 1) & 1);
            asm volatile("cp.async.wait_group 1;\n");
        } else {
            asm volatile("cp.async.wait_group 0;\n");
        }
        __syncthreads();

        const float* A = smem + (kt & 1) * BUF;
        const float* B = A + TILE_M * SSTR;

        #pragma unroll
        for (int kk = 0; kk < TILE_K; kk += 8) {
            uint32_t af[4][4], bf[8][2];
            #pragma unroll
            for (int mi = 0; mi < 4; mi++) {
                const float* p = A + (wm * 64 + mi * 16 + g) * SSTR + kk + t4;
                af[mi][0] = f2tf(p[0]);
                af[mi][1] = f2tf(p[8 * SSTR]);
                af[mi][2] = f2tf(p[4]);
                af[mi][3] = f2tf(p[8 * SSTR + 4]);
            }
            #pragma unroll
            for (int ni = 0; ni < 8; ni++) {
                const float* p = B + (wn * 64 + ni * 8 + g) * SSTR + kk + t4;
                bf[ni][0] = f2tf(p[0]);
                bf[ni][1] = f2tf(p[4]);
            }
            #pragma unroll
            for (int mi = 0; mi < 4; mi++)
                #pragma unroll
                for (int ni = 0; ni < 8; ni++)
                    asm volatile(
                        "mma.sync.aligned.m16n8k8.row.col.f32.tf32.tf32.f32 "
                        "{%0,%1,%2,%3}, {%4,%5,%6,%7}, {%8,%9}, {%0,%1,%2,%3};\n"
                        : "+f"(acc[mi][ni][0]), "+f"(acc[mi][ni][1]),
                          "+f"(acc[mi][ni][2]), "+f"(acc[mi][ni][3])
                        : "r"(af[mi][0]), "r"(af[mi][1]), "r"(af[mi][2]), "r"(af[mi][3]),
                          "r"(bf[ni][0]), "r"(bf[ni][1]));
        }
        __syncthreads();
    }

    // ---- Epilogue: RoPE + (b, h, s, d) scatter ----
    const size_t QSZ = (size_t)BSZ * NHEADS * SEQ * HD;   // 67108864
    const size_t KSZ = (size_t)BSZ * NKV    * SEQ * HD;   // 16777216
    size_t obase; int h, nh;
    if (head < NHEADS)            { obase = 0;         h = head;                nh = NHEADS; }
    else if (head < NHEADS + NKV) { obase = QSZ;       h = head - NHEADS;       nh = NKV; }
    else                          { obase = QSZ + KSZ; h = head - NHEADS - NKV; nh = NKV; }
    const bool rope  = head < NHEADS + NKV;
    const int  bb    = m0 >> 12;          // 128-row tile never straddles a batch
    const int  sbase = m0 & (SEQ - 1);
    float* ob = out + obase + ((size_t)bb * nh + h) * (size_t)SEQ * HD;

    #pragma unroll
    for (int mi = 0; mi < 4; mi++) {
        #pragma unroll
        for (int ni = 0; ni < 8; ni++) {
            const int d = wn * 64 + ni * 8 + t4 * 2;   // even: RoPE pair (d, d+1) in-thread
            const int i = d >> 1;
            #pragma unroll
            for (int hl = 0; hl < 2; hl++) {
                const int s = sbase + wm * 64 + mi * 16 + g + hl * 8;
                float v0 = acc[mi][ni][hl * 2 + 0];
                float v1 = acc[mi][ni][hl * 2 + 1];
                if (rope) {
                    const float cs = cosT[s * 64 + i];
                    const float sn = sinT[s * 64 + i];
                    const float r0 = v0 * cs - v1 * sn;
                    const float r1 = v0 * sn + v1 * cs;
                    v0 = r0; v1 = r1;
                }
                float2 vv; vv.x = v0; vv.y = v1;
                *reinterpret_cast<float2*>(ob + (size_t)s * HD + d) = vv;
            }
        }
    }
}

extern "C" void kernel_launch(void* const* d_in, const int* in_sizes, int n_in,
                              void* d_out, int out_size)
{
    const float* x    = (const float*)d_in[0];
    const float* wq   = (const float*)d_in[1];
    const float* wk   = (const float*)d_in[2];
    const float* wv   = (const float*)d_in[3];
    const float* cosT = (const float*)d_in[4];
    const float* sinT = (const float*)d_in[5];
    float* out = (float*)d_out;

    const int smem_bytes = 2 * (TILE_M * SSTR + TILE_N * SSTR) * 4;  // 73728
    cudaFuncSetAttribute(qkv_rope_kernel,
                         cudaFuncAttributeMaxDynamicSharedMemorySize, smem_bytes);

    dim3 grid(NHEADS + 2 * NKV /*48 head-tiles*/, (BSZ * SEQ) / TILE_M /*128 row-tiles*/);
    qkv_rope_kernel<<<grid, THREADS, smem_bytes>>>(x, wq, wk, wv, cosT, sinT, out);
}